// round 14
// baseline (speedup 1.0000x reference)
#include <cuda_runtime.h>
#include <cuda_fp16.h>
#include <cstdint>

#define Bq   32
#define Nn   512
#define Tt   (Bq*Nn)          // 16384 tokens
#define Fd   1024
#define Md   256
#define Ee   8
#define TT   128              // token tile
#define NTILES (Tt/TT + Ee)   // 136 max padded tiles
#define SORT_SZ (Tt + Ee*TT)  // 17408
#define OUTD 17
#define EPSV 1e-8f

// layer-1 GEMM tiling (fp16 operands, fp32 accum)
#define KC 32                 // K halves per stage
#define KSTEPS (Fd/KC)        // 32
#define WPH 40                // stage row pitch in halves (32 + 8 pad)
#define STAGE_B (256*WPH*2)   // 20480 B
#define NST 3
#define EPH 136               // epilogue pitch (halves)
#define GEMM_SMEM (NST*STAGE_B + 512)   // 61952

// tail2 smem layout (bytes)
#define T2_PH 264                       // h1 / w2t row pitch in halves
#define T2_SH    0                      // 128 x 264 half
#define T2_SW2   (T2_SH + 128*T2_PH*2)  // 64 x 264 half
#define T2_SH2   (T2_SW2 + 64*T2_PH*2)  // 128 x 68 float
#define T2_SW3   (T2_SH2 + 128*68*4)
#define T2_SW4   (T2_SW3 + 64*32*4)
#define T2_SR2   (T2_SW4 + 32*14*4)
#define T2_SH3   (T2_SR2 + 256*3*4)
#define T2_SB2   (T2_SH3 + 8*36*4)
#define T2_SB3   (T2_SB2 + 64*4)
#define T2_SB4   (T2_SB3 + 32*4)
#define T2_SRB2  (T2_SB4 + 14*4)
#define TAIL2_SMEM (T2_SRB2 + 16*4)

// merged prep grid split
#define PREP_XH_BLKS  (Tt*Fd/8/256)     // 8192
#define PREP_WT_BLKS  4096
#define PREP_W2T_BLKS 128
#define PREP_BLKS (PREP_XH_BLKS + PREP_WT_BLKS + PREP_W2T_BLKS)

// ---------------- device scratch ----------------
__device__ int    g_partial[64][Ee];
__device__ int    g_fill[Ee];
__device__ int    g_off[Ee+1];
__device__ int    g_sorted[SORT_SZ];
__device__ __half g_h1h[(size_t)SORT_SZ*Md];
__device__ __half g_r1h[(size_t)SORT_SZ*Md];
__device__ __half g_w1h[(size_t)Ee*Md*Fd];   // W1^T [e][n][k] fp16
__device__ __half g_r1w[(size_t)Ee*Md*Fd];   // R1^T
__device__ __half g_w2t[(size_t)Ee*64*Md];   // W2^T [e][n][k] fp16
__device__ __half g_xh [(size_t)Tt*Fd];      // nodes in fp16

// ---------------- helpers ----------------
__device__ __forceinline__ uint32_t s2u(const void* p) {
    return (uint32_t)__cvta_generic_to_shared((void*)p);
}
__device__ __forceinline__ void cpa16(uint32_t d, const void* s) {
    asm volatile("cp.async.cg.shared.global [%0], [%1], 16;" :: "r"(d), "l"(s));
}
__device__ __forceinline__ void cpa16z(uint32_t d, const void* s, uint32_t sz) {
    asm volatile("cp.async.cg.shared.global [%0], [%1], 16, %2;" :: "r"(d), "l"(s), "r"(sz));
}
__device__ __forceinline__ void ldsm4(uint32_t &r0, uint32_t &r1, uint32_t &r2, uint32_t &r3,
                                      uint32_t addr) {
    asm volatile("ldmatrix.sync.aligned.m8n8.x4.shared.b16 {%0,%1,%2,%3}, [%4];"
                 : "=r"(r0), "=r"(r1), "=r"(r2), "=r"(r3) : "r"(addr));
}
#define MMA16816(C, A, B)                                                        \
    asm volatile(                                                                \
        "mma.sync.aligned.m16n8k16.row.col.f32.f16.f16.f32 "                     \
        "{%0,%1,%2,%3}, {%4,%5,%6,%7}, {%8,%9}, {%0,%1,%2,%3};"                  \
        : "+f"((C)[0]), "+f"((C)[1]), "+f"((C)[2]), "+f"((C)[3])                 \
        : "r"((A)[0]), "r"((A)[1]), "r"((A)[2]), "r"((A)[3]),                    \
          "r"((B)[0]), "r"((B)[1]))

// ---------------- sort prep ----------------
__global__ void k_count(const int* __restrict__ sem) {
    __shared__ int h[Ee];
    int tid = threadIdx.x;
    if (tid < Ee) h[tid] = 0;
    __syncthreads();
    atomicAdd(&h[sem[blockIdx.x*256 + tid]], 1);
    __syncthreads();
    if (tid < Ee) g_partial[blockIdx.x][tid] = h[tid];
}
__global__ void k_offsets() {
    __shared__ int scnt[Ee];
    __shared__ int so[Ee+1];
    int tid = threadIdx.x;
    if (tid < Ee) {
        int s = 0;
        for (int b = 0; b < 64; b++) s += g_partial[b][tid];
        scnt[tid] = s;
        g_fill[tid] = 0;
    }
    __syncthreads();
    if (tid == 0) {
        int acc = 0;
        for (int e = 0; e < Ee; e++) {
            so[e] = acc; g_off[e] = acc;
            acc += ((scnt[e] + TT - 1) / TT) * TT;
        }
        so[Ee] = acc; g_off[Ee] = acc;
    }
    __syncthreads();
    for (int e = 0; e < Ee; e++) {
        int cnt = scnt[e], base = so[e], padded = so[e+1] - base;
        for (int i = cnt + tid; i < padded; i += 256)
            g_sorted[base + i] = -1;
    }
}
__global__ void k_scatter(const int* __restrict__ sem) {
    int t = blockIdx.x*256 + threadIdx.x;
    int e = sem[t];
    int pos = g_off[e] + atomicAdd(&g_fill[e], 1);
    g_sorted[pos] = t;
}

// ---------------- merged prep: X->fp16, W1/R1 transpose, W2 transpose ----------------
__global__ void k_prep(const float* __restrict__ nodes,
                       const float* __restrict__ W1, const float* __restrict__ R1,
                       const float* __restrict__ W2) {
    int bid = blockIdx.x;
    int tid = threadIdx.x;

    if (bid < PREP_XH_BLKS) {
        size_t i = ((size_t)bid*256 + tid) * 8;
        float4 v0 = *reinterpret_cast<const float4*>(nodes + i);
        float4 v1 = *reinterpret_cast<const float4*>(nodes + i + 4);
        __half2 h[4];
        h[0] = __floats2half2_rn(v0.x, v0.y);
        h[1] = __floats2half2_rn(v0.z, v0.w);
        h[2] = __floats2half2_rn(v1.x, v1.y);
        h[3] = __floats2half2_rn(v1.z, v1.w);
        *reinterpret_cast<uint4*>(g_xh + i) = *reinterpret_cast<uint4*>(h);
        return;
    }

    __shared__ float tile[32][33];
    int tx = tid & 31, ty = tid >> 5;

    if (bid < PREP_XH_BLKS + PREP_WT_BLKS) {
        int bz = bid - PREP_XH_BLKS;          // [0, 4096)
        int z   = bz >> 8;                    // mat*8 + e
        int rem = bz & 255;
        int k0 = (rem & 31) * 32;
        int n0 = (rem >> 5) * 32;
        int mat = z >> 3, e = z & 7;
        const float* src = (mat ? R1 : W1) + (size_t)e * Fd * Md;
        __half*      dst = (mat ? g_r1w : g_w1h) + (size_t)e * Md * Fd;
        for (int j = ty; j < 32; j += 8)
            tile[j][tx] = src[(size_t)(k0 + j) * Md + n0 + tx];
        __syncthreads();
        for (int j = ty; j < 32; j += 8)
            dst[(size_t)(n0 + j) * Fd + k0 + tx] = __float2half_rn(tile[tx][j]);
        return;
    }

    {
        int bz = bid - PREP_XH_BLKS - PREP_WT_BLKS;   // [0, 128)
        int k0 = (bz & 7) * 32;
        int n0 = ((bz >> 3) & 1) * 32;
        int e  = bz >> 4;
        const float* src = W2 + (size_t)e * Md * 64;
        __half*      dst = g_w2t + (size_t)e * 64 * Md;
        for (int j = ty; j < 32; j += 8)
            tile[j][tx] = src[(size_t)(k0 + j) * 64 + n0 + tx];
        __syncthreads();
        for (int j = ty; j < 32; j += 8)
            dst[(size_t)(n0 + j) * Md + k0 + tx] = __float2half_rn(tile[tx][j]);
    }
}

// ---------------- layer-1 GEMM: mma.sync fp16 + ldmatrix, 3-stage pipeline ----------------
// grid (NTILES, 4): y>>1 = branch (0:W1->g_h1h, 1:R1->g_r1h), y&1 = column half.
__global__ void __launch_bounds__(256, 2)
k_gemm1_mma(const float* __restrict__ b1, const float* __restrict__ rb1)
{
    extern __shared__ float sm[];
    __shared__ int soff[Ee+1];

    int tid = threadIdx.x;
    if (tid < Ee+1) soff[tid] = g_off[tid];
    __syncthreads();

    int p0 = blockIdx.x * TT;
    if (p0 >= soff[Ee]) return;
    int e = 0;
    while (e < Ee-1 && p0 >= soff[e+1]) e++;

    bool rotb = (blockIdx.y >= 2);
    int  half = blockIdx.y & 1;
    const __half* Wt   = (rotb ? g_r1w : g_w1h) + (size_t)(e*Md + half*128) * Fd;
    const float*  bias = (rotb ? rb1 : b1) + e*Md + half*128;
    __half*       dst  = rotb ? g_r1h : g_h1h;

    float* sbias = (float*)((char*)sm + NST*STAGE_B);
    for (int i = tid; i < 128; i += 256) sbias[i] = bias[i];

    int row  = tid >> 1;
    int hsel = tid & 1;
    int t_x = g_sorted[p0 + row];
    uint32_t xsz = (t_x >= 0) ? 16u : 0u;
    const __half* xsrc = g_xh + (size_t)(t_x >= 0 ? t_x : 0) * Fd + hsel*16;
    const __half* wsrc = Wt + (size_t)row * Fd + hsel*16;

    uint32_t smU  = s2u(sm);
    uint32_t wdst = smU + (uint32_t)row*(WPH*2) + hsel*32;
    uint32_t xdst = smU + (uint32_t)(128 + row)*(WPH*2) + hsel*32;

    auto load_stage = [&](int s, int b) {
        uint32_t bo = (uint32_t)b * STAGE_B;
        const __half* ws = wsrc + s*KC;
        cpa16(wdst + bo,      ws);
        cpa16(wdst + bo + 16, ws + 8);
        const __half* xs = xsrc + s*KC;
        cpa16z(xdst + bo,      xs,     xsz);
        cpa16z(xdst + bo + 16, xs + 8, xsz);
        asm volatile("cp.async.commit_group;" ::: "memory");
    };

    int wid = tid >> 5;
    int lane = tid & 31;
    int g = lane >> 2, tig = lane & 3;
    int warpM = wid & 3, warpN = wid >> 2;

    uint32_t aoff[2];
    {
        int r16 = ((lane >> 3) & 1) * 8 + (lane & 7);
        int bhi = (lane >> 4) * 16;
        #pragma unroll
        for (int mt = 0; mt < 2; mt++) {
            int m = warpM*32 + mt*16 + r16;
            aoff[mt] = (uint32_t)m*(WPH*2) + bhi;
        }
    }
    uint32_t boff[4];
    {
        int tok = ((lane >> 4) * 8) + (lane & 7);
        int bhi = ((lane >> 3) & 1) * 16;
        #pragma unroll
        for (int p = 0; p < 4; p++) {
            int n = warpN*64 + p*16 + tok;
            boff[p] = (uint32_t)(128 + n)*(WPH*2) + bhi;
        }
    }

    float c[2][8][4];
    #pragma unroll
    for (int mt = 0; mt < 2; mt++)
        #pragma unroll
        for (int nt = 0; nt < 8; nt++)
            #pragma unroll
            for (int r = 0; r < 4; r++) c[mt][nt][r] = 0.f;

    load_stage(0, 0);
    load_stage(1, 1);

    int b = 0, bn = 2;   // compute buffer, next-load buffer
    for (int s = 0; s < KSTEPS; s++) {
        if (s + 1 < KSTEPS) asm volatile("cp.async.wait_group 1;" ::: "memory");
        else                asm volatile("cp.async.wait_group 0;" ::: "memory");
        __syncthreads();
        if (s + 2 < KSTEPS) load_stage(s + 2, bn);

        uint32_t stU = smU + (uint32_t)b * STAGE_B;

        #pragma unroll
        for (int kk = 0; kk < 2; kk++) {
            uint32_t ko = kk*32;
            uint32_t a[2][4];
            ldsm4(a[0][0], a[0][1], a[0][2], a[0][3], stU + aoff[0] + ko);
            ldsm4(a[1][0], a[1][1], a[1][2], a[1][3], stU + aoff[1] + ko);

            uint32_t bb[8][2];
            #pragma unroll
            for (int p = 0; p < 4; p++) {
                uint32_t r0, r1, r2, r3;
                ldsm4(r0, r1, r2, r3, stU + boff[p] + ko);
                bb[2*p+0][0] = r0; bb[2*p+0][1] = r1;
                bb[2*p+1][0] = r2; bb[2*p+1][1] = r3;
            }
            #pragma unroll
            for (int mt = 0; mt < 2; mt++)
                #pragma unroll
                for (int nt = 0; nt < 8; nt++)
                    MMA16816(c[mt][nt], a[mt], bb[nt]);
        }
        b = (b + 1) % NST;
        bn = (bn + 1) % NST;
    }
    __syncthreads();

    // epilogue: bias + relu + fp16, stage through smem, coalesced store
    __half* ep = (__half*)sm;
    #pragma unroll
    for (int mt = 0; mt < 2; mt++) {
        int m = warpM*32 + mt*16 + g;
        float bz0 = sbias[m], bz1 = sbias[m + 8];
        #pragma unroll
        for (int nt = 0; nt < 8; nt++) {
            int n = warpN*64 + nt*8 + 2*tig;
            ep[(size_t)n*EPH + m]         = __float2half_rn(fmaxf(c[mt][nt][0] + bz0, 0.f));
            ep[(size_t)(n+1)*EPH + m]     = __float2half_rn(fmaxf(c[mt][nt][1] + bz0, 0.f));
            ep[(size_t)n*EPH + m + 8]     = __float2half_rn(fmaxf(c[mt][nt][2] + bz1, 0.f));
            ep[(size_t)(n+1)*EPH + m + 8] = __float2half_rn(fmaxf(c[mt][nt][3] + bz1, 0.f));
        }
    }
    __syncthreads();

    {
        int r2 = tid >> 1, h2 = tid & 1;
        const __half* srow = ep + (size_t)r2*EPH + h2*64;
        __half* drow = dst + (size_t)(p0 + r2)*Md + half*128 + h2*64;
        #pragma unroll
        for (int i = 0; i < 8; i++)
            *reinterpret_cast<uint4*>(drow + i*8) =
                *reinterpret_cast<const uint4*>(srow + i*8);
    }
}

// ---------------- tail2: mma layer2 + SIMT layers 3/4 + rot ----------------
__global__ void __launch_bounds__(256, 1)
k_tail2(const float* __restrict__ b2,
        const float* __restrict__ W3, const float* __restrict__ b3,
        const float* __restrict__ W4, const float* __restrict__ b4,
        const float* __restrict__ R2, const float* __restrict__ rb2,
        const int* __restrict__ lengths, float* __restrict__ out)
{
    extern __shared__ char smc[];
    __shared__ int soff[Ee+1];
    int tid = threadIdx.x;
    if (tid < Ee+1) soff[tid] = g_off[tid];
    __syncthreads();

    int p0 = blockIdx.x * TT;
    if (p0 >= soff[Ee]) return;
    int e = 0;
    while (e < Ee-1 && p0 >= soff[e+1]) e++;

    uint32_t smU = s2u(smc);
    float* sh2  = (float*)(smc + T2_SH2);
    float* sW3  = (float*)(smc + T2_SW3);
    float* sW4  = (float*)(smc + T2_SW4);
    float* sR2  = (float*)(smc + T2_SR2);
    float* sh3  = (float*)(smc + T2_SH3);
    float* sb2  = (float*)(smc + T2_SB2);
    float* sb3  = (float*)(smc + T2_SB3);
    float* sb4  = (float*)(smc + T2_SB4);
    float* srb2 = (float*)(smc + T2_SRB2);

    {
        int row = tid >> 1, hs = tid & 1;
        const __half* src = g_h1h + (size_t)(p0 + row)*Md + hs*128;
        uint32_t d = smU + T2_SH + (uint32_t)row*(T2_PH*2) + hs*256;
        #pragma unroll
        for (int i = 0; i < 16; i++) cpa16(d + i*16, src + i*8);
    }
    {
        int row = tid >> 2, hs = tid & 3;
        const __half* src = g_w2t + (size_t)e*64*Md + (size_t)row*Md + hs*64;
        uint32_t d = smU + T2_SW2 + (uint32_t)row*(T2_PH*2) + hs*128;
        #pragma unroll
        for (int i = 0; i < 8; i++) cpa16(d + i*16, src + i*8);
    }
    asm volatile("cp.async.commit_group;" ::: "memory");

    const float* gW3 = W3 + e*64*32;
    for (int i = tid; i < 64*32; i += 256) sW3[i] = gW3[i];
    const float* gW4 = W4 + e*32*14;
    for (int i = tid; i < 32*14; i += 256) sW4[i] = gW4[i];
    const float* gR2 = R2 + e*Md*3;
    for (int i = tid; i < Md*3; i += 256) sR2[i] = gR2[i];
    if (tid < 64) sb2[tid]  = b2[e*64 + tid];
    if (tid < 32) sb3[tid]  = b3[e*32 + tid];
    if (tid < 14) sb4[tid]  = b4[e*14 + tid];
    if (tid < 3)  srb2[tid] = rb2[e*3 + tid];

    asm volatile("cp.async.wait_group 0;" ::: "memory");
    __syncthreads();

    int wid = tid >> 5, lane = tid & 31;
    int g = lane >> 2, tig = lane & 3;
    int warpM = wid & 3, warpN = wid >> 2;

    uint32_t aoff[2];
    {
        int r16 = ((lane >> 3) & 1) * 8 + (lane & 7);
        int bhi = (lane >> 4) * 16;
        #pragma unroll
        for (int mt = 0; mt < 2; mt++) {
            int m = warpM*32 + mt*16 + r16;
            aoff[mt] = T2_SH + (uint32_t)m*(T2_PH*2) + bhi;
        }
    }
    uint32_t boff[2];
    {
        int nn = ((lane >> 4) * 8) + (lane & 7);
        int bhi = ((lane >> 3) & 1) * 16;
        #pragma unroll
        for (int p = 0; p < 2; p++) {
            int n = warpN*32 + p*16 + nn;
            boff[p] = T2_SW2 + (uint32_t)n*(T2_PH*2) + bhi;
        }
    }

    float c[2][4][4];
    #pragma unroll
    for (int mt = 0; mt < 2; mt++)
        #pragma unroll
        for (int nt = 0; nt < 4; nt++)
            #pragma unroll
            for (int r = 0; r < 4; r++) c[mt][nt][r] = 0.f;

    #pragma unroll
    for (int kk = 0; kk < 16; kk++) {
        uint32_t ko = kk*32;
        uint32_t a[2][4];
        ldsm4(a[0][0], a[0][1], a[0][2], a[0][3], smU + aoff[0] + ko);
        ldsm4(a[1][0], a[1][1], a[1][2], a[1][3], smU + aoff[1] + ko);
        uint32_t bb[4][2];
        #pragma unroll
        for (int p = 0; p < 2; p++) {
            uint32_t r0, r1, r2, r3;
            ldsm4(r0, r1, r2, r3, smU + boff[p] + ko);
            bb[2*p+0][0] = r0; bb[2*p+0][1] = r1;
            bb[2*p+1][0] = r2; bb[2*p+1][1] = r3;
        }
        #pragma unroll
        for (int mt = 0; mt < 2; mt++)
            #pragma unroll
            for (int nt = 0; nt < 4; nt++)
                MMA16816(c[mt][nt], a[mt], bb[nt]);
    }

    #pragma unroll
    for (int mt = 0; mt < 2; mt++) {
        int m0 = warpM*32 + mt*16 + g;
        #pragma unroll
        for (int nt = 0; nt < 4; nt++) {
            int n = warpN*32 + nt*8 + 2*tig;
            float bz0 = sb2[n], bz1 = sb2[n+1];
            sh2[(size_t)m0*68 + n]         = fmaxf(c[mt][nt][0] + bz0, 0.f);
            sh2[(size_t)m0*68 + n + 1]     = fmaxf(c[mt][nt][1] + bz1, 0.f);
            sh2[(size_t)(m0+8)*68 + n]     = fmaxf(c[mt][nt][2] + bz0, 0.f);
            sh2[(size_t)(m0+8)*68 + n + 1] = fmaxf(c[mt][nt][3] + bz1, 0.f);
        }
    }
    __syncthreads();

    float* h3w = sh3 + wid*36;
    for (int it = 0; it < 16; it++) {
        int p = p0 + wid*16 + it;
        int t = g_sorted[p];
        if (t < 0) continue;

        const float* h2row = sh2 + (size_t)(wid*16 + it)*68;

        float a = sb3[lane];
        #pragma unroll
        for (int h = 0; h < 64; h++) a += h2row[h] * sW3[h*32 + lane];
        h3w[lane] = fmaxf(a, 0.f);
        __syncwarp();

        float y = 0.f;
        if (lane < 14) {
            y = sb4[lane];
            #pragma unroll
            for (int gg = 0; gg < 32; gg++) y += h3w[gg] * sW4[gg*14 + lane];
        }

        float r0 = 0.f, r1v = 0.f, r2 = 0.f;
        {
            uint4 rv = *reinterpret_cast<const uint4*>(g_r1h + (size_t)p*Md + lane*8);
            const __half2* hp = reinterpret_cast<const __half2*>(&rv);
            #pragma unroll
            for (int u = 0; u < 4; u++) {
                float2 f = __half22float2(hp[u]);
                int m = lane*8 + 2*u;
                r0  += f.x * sR2[m*3 + 0] + f.y * sR2[(m+1)*3 + 0];
                r1v += f.x * sR2[m*3 + 1] + f.y * sR2[(m+1)*3 + 1];
                r2  += f.x * sR2[m*3 + 2] + f.y * sR2[(m+1)*3 + 2];
            }
        }
        #pragma unroll
        for (int s = 16; s > 0; s >>= 1) {
            r0  += __shfl_xor_sync(0xffffffff, r0, s);
            r1v += __shfl_xor_sync(0xffffffff, r1v, s);
            r2  += __shfl_xor_sync(0xffffffff, r2, s);
        }

        int b = t >> 9, n = t & (Nn - 1);
        bool masked = (n >= lengths[b]);
        float* op = out + (size_t)t*OUTD;
        if (masked) {
            if (lane < OUTD) op[lane] = EPSV;
        } else {
            if (lane < 14) op[lane] = y;
            if (lane == 0) {
                op[14] = r0  + srb2[0];
                op[15] = r1v + srb2[1];
                op[16] = r2  + srb2[2];
            }
        }
    }
}

extern "C" void kernel_launch(void* const* d_in, const int* in_sizes, int n_in,
                              void* d_out, int out_size) {
    const float* nodes   = (const float*)d_in[0];
    const int*   sem     = (const int*)  d_in[1];
    const int*   lengths = (const int*)  d_in[2];
    const float* W1 = (const float*)d_in[3];  const float* b1  = (const float*)d_in[4];
    const float* W2 = (const float*)d_in[5];  const float* b2  = (const float*)d_in[6];
    const float* W3 = (const float*)d_in[7];  const float* b3  = (const float*)d_in[8];
    const float* W4 = (const float*)d_in[9];  const float* b4  = (const float*)d_in[10];
    const float* R1 = (const float*)d_in[11]; const float* rb1 = (const float*)d_in[12];
    const float* R2 = (const float*)d_in[13]; const float* rb2 = (const float*)d_in[14];
    float* out = (float*)d_out;

    cudaFuncSetAttribute(k_gemm1_mma, cudaFuncAttributeMaxDynamicSharedMemorySize, GEMM_SMEM);
    cudaFuncSetAttribute(k_tail2, cudaFuncAttributeMaxDynamicSharedMemorySize, TAIL2_SMEM);

    // Fork: sort chain on side stream, prep on main stream, join before gemm.
    // Host-side stream/event creation only (no device memory). Not destroyed:
    // destroying capture-referenced objects mid-capture is illegal; the few
    // host objects leaked per call (~3 calls total) are harmless.
    cudaStream_t s2;
    cudaStreamCreateWithFlags(&s2, cudaStreamNonBlocking);
    cudaEvent_t eFork, eJoin;
    cudaEventCreateWithFlags(&eFork, cudaEventDisableTiming);
    cudaEventCreateWithFlags(&eJoin, cudaEventDisableTiming);

    cudaEventRecord(eFork, 0);
    cudaStreamWaitEvent(s2, eFork, 0);
    k_count  <<<Tt/256, 256, 0, s2>>>(sem);
    k_offsets<<<1, 256, 0, s2>>>();
    k_scatter<<<Tt/256, 256, 0, s2>>>(sem);
    cudaEventRecord(eJoin, s2);

    k_prep   <<<PREP_BLKS, 256>>>(nodes, W1, R1, W2);   // main stream, concurrent

    cudaStreamWaitEvent(0, eJoin, 0);
    {
        dim3 g1(NTILES, 4);
        k_gemm1_mma<<<g1, 256, GEMM_SMEM>>>(b1, rb1);
    }
    k_tail2<<<NTILES, 256, TAIL2_SMEM>>>(b2, W3, b3, W4, b4, R2, rb2, lengths, out);
}

// round 15
// speedup vs baseline: 1.3443x; 1.3443x over previous
#include <cuda_runtime.h>
#include <cuda_fp16.h>
#include <cstdint>

#define Bq   32
#define Nn   512
#define Tt   (Bq*Nn)          // 16384 tokens
#define Fd   1024
#define Md   256
#define Ee   8
#define TT   128              // token tile
#define NTILES (Tt/TT + Ee)   // 136 max padded tiles
#define GRIDX (NTILES/2)      // 68 persistent CTAs per branch-column
#define SORT_SZ (Tt + Ee*TT)  // 17408
#define OUTD 17
#define EPSV 1e-8f

// layer-1 GEMM tiling (fp16 operands, fp32 accum)
#define KC 32                 // K halves per stage
#define KSTEPS (Fd/KC)        // 32
#define WPH 40                // stage row pitch in halves (32 + 8 pad)
#define STAGE_B (256*WPH*2)   // 20480 B
#define NST 3
#define EPH 136               // epilogue pitch (halves)
#define GEMM_SMEM (NST*STAGE_B + 512)   // 61952

// tail2 smem layout (bytes)
#define T2_PH 264                       // h1 / w2t row pitch in halves
#define T2_SH    0                      // 128 x 264 half
#define T2_SW2   (T2_SH + 128*T2_PH*2)  // 64 x 264 half
#define T2_SH2   (T2_SW2 + 64*T2_PH*2)  // 128 x 68 float
#define T2_SW3   (T2_SH2 + 128*68*4)
#define T2_SW4   (T2_SW3 + 64*32*4)
#define T2_SR2   (T2_SW4 + 32*14*4)
#define T2_SH3   (T2_SR2 + 256*3*4)
#define T2_SB2   (T2_SH3 + 8*36*4)
#define T2_SB3   (T2_SB2 + 64*4)
#define T2_SB4   (T2_SB3 + 32*4)
#define T2_SRB2  (T2_SB4 + 14*4)
#define TAIL2_SMEM (T2_SRB2 + 16*4)

// merged prep grid split
#define PREP_XH_BLKS  (Tt*Fd/8/256)     // 8192
#define PREP_WT_BLKS  4096
#define PREP_W2T_BLKS 128
#define PREP_BLKS (PREP_XH_BLKS + PREP_WT_BLKS + PREP_W2T_BLKS)

// ---------------- device scratch ----------------
__device__ int    g_partial[64][Ee];
__device__ int    g_fill[Ee];
__device__ int    g_off[Ee+1];
__device__ int    g_sorted[SORT_SZ];
__device__ __half g_h1h[(size_t)SORT_SZ*Md];
__device__ __half g_r1h[(size_t)SORT_SZ*Md];
__device__ __half g_w1h[(size_t)Ee*Md*Fd];   // W1^T [e][n][k] fp16
__device__ __half g_r1w[(size_t)Ee*Md*Fd];   // R1^T
__device__ __half g_w2t[(size_t)Ee*64*Md];   // W2^T [e][n][k] fp16
__device__ __half g_xh [(size_t)Tt*Fd];      // nodes in fp16

// ---------------- helpers ----------------
__device__ __forceinline__ uint32_t s2u(const void* p) {
    return (uint32_t)__cvta_generic_to_shared((void*)p);
}
__device__ __forceinline__ void cpa16(uint32_t d, const void* s) {
    asm volatile("cp.async.cg.shared.global [%0], [%1], 16;" :: "r"(d), "l"(s));
}
__device__ __forceinline__ void cpa16z(uint32_t d, const void* s, uint32_t sz) {
    asm volatile("cp.async.cg.shared.global [%0], [%1], 16, %2;" :: "r"(d), "l"(s), "r"(sz));
}
__device__ __forceinline__ void ldsm4(uint32_t &r0, uint32_t &r1, uint32_t &r2, uint32_t &r3,
                                      uint32_t addr) {
    asm volatile("ldmatrix.sync.aligned.m8n8.x4.shared.b16 {%0,%1,%2,%3}, [%4];"
                 : "=r"(r0), "=r"(r1), "=r"(r2), "=r"(r3) : "r"(addr));
}
#define MMA16816(C, A, B)                                                        \
    asm volatile(                                                                \
        "mma.sync.aligned.m16n8k16.row.col.f32.f16.f16.f32 "                     \
        "{%0,%1,%2,%3}, {%4,%5,%6,%7}, {%8,%9}, {%0,%1,%2,%3};"                  \
        : "+f"((C)[0]), "+f"((C)[1]), "+f"((C)[2]), "+f"((C)[3])                 \
        : "r"((A)[0]), "r"((A)[1]), "r"((A)[2]), "r"((A)[3]),                    \
          "r"((B)[0]), "r"((B)[1]))

// ---------------- sort prep ----------------
__global__ void k_count(const int* __restrict__ sem) {
    __shared__ int h[Ee];
    int tid = threadIdx.x;
    if (tid < Ee) h[tid] = 0;
    __syncthreads();
    atomicAdd(&h[sem[blockIdx.x*256 + tid]], 1);
    __syncthreads();
    if (tid < Ee) g_partial[blockIdx.x][tid] = h[tid];
}
__global__ void k_offsets() {
    __shared__ int scnt[Ee];
    __shared__ int so[Ee+1];
    int tid = threadIdx.x;
    if (tid < Ee) {
        int s = 0;
        for (int b = 0; b < 64; b++) s += g_partial[b][tid];
        scnt[tid] = s;
        g_fill[tid] = 0;
    }
    __syncthreads();
    if (tid == 0) {
        int acc = 0;
        for (int e = 0; e < Ee; e++) {
            so[e] = acc; g_off[e] = acc;
            acc += ((scnt[e] + TT - 1) / TT) * TT;
        }
        so[Ee] = acc; g_off[Ee] = acc;
    }
    __syncthreads();
    for (int e = 0; e < Ee; e++) {
        int cnt = scnt[e], base = so[e], padded = so[e+1] - base;
        for (int i = cnt + tid; i < padded; i += 256)
            g_sorted[base + i] = -1;
    }
}
__global__ void k_scatter(const int* __restrict__ sem) {
    int t = blockIdx.x*256 + threadIdx.x;
    int e = sem[t];
    int pos = g_off[e] + atomicAdd(&g_fill[e], 1);
    g_sorted[pos] = t;
}

// ---------------- merged prep: X->fp16, W1/R1 transpose, W2 transpose ----------------
__global__ void k_prep(const float* __restrict__ nodes,
                       const float* __restrict__ W1, const float* __restrict__ R1,
                       const float* __restrict__ W2) {
    int bid = blockIdx.x;
    int tid = threadIdx.x;

    if (bid < PREP_XH_BLKS) {
        size_t i = ((size_t)bid*256 + tid) * 8;
        float4 v0 = *reinterpret_cast<const float4*>(nodes + i);
        float4 v1 = *reinterpret_cast<const float4*>(nodes + i + 4);
        __half2 h[4];
        h[0] = __floats2half2_rn(v0.x, v0.y);
        h[1] = __floats2half2_rn(v0.z, v0.w);
        h[2] = __floats2half2_rn(v1.x, v1.y);
        h[3] = __floats2half2_rn(v1.z, v1.w);
        *reinterpret_cast<uint4*>(g_xh + i) = *reinterpret_cast<uint4*>(h);
        return;
    }

    __shared__ float tile[32][33];
    int tx = tid & 31, ty = tid >> 5;

    if (bid < PREP_XH_BLKS + PREP_WT_BLKS) {
        int bz = bid - PREP_XH_BLKS;          // [0, 4096)
        int z   = bz >> 8;                    // mat*8 + e
        int rem = bz & 255;
        int k0 = (rem & 31) * 32;
        int n0 = (rem >> 5) * 32;
        int mat = z >> 3, e = z & 7;
        const float* src = (mat ? R1 : W1) + (size_t)e * Fd * Md;
        __half*      dst = (mat ? g_r1w : g_w1h) + (size_t)e * Md * Fd;
        for (int j = ty; j < 32; j += 8)
            tile[j][tx] = src[(size_t)(k0 + j) * Md + n0 + tx];
        __syncthreads();
        for (int j = ty; j < 32; j += 8)
            dst[(size_t)(n0 + j) * Fd + k0 + tx] = __float2half_rn(tile[tx][j]);
        return;
    }

    {
        int bz = bid - PREP_XH_BLKS - PREP_WT_BLKS;   // [0, 128)
        int k0 = (bz & 7) * 32;
        int n0 = ((bz >> 3) & 1) * 32;
        int e  = bz >> 4;
        const float* src = W2 + (size_t)e * Md * 64;
        __half*      dst = g_w2t + (size_t)e * 64 * Md;
        for (int j = ty; j < 32; j += 8)
            tile[j][tx] = src[(size_t)(k0 + j) * 64 + n0 + tx];
        __syncthreads();
        for (int j = ty; j < 32; j += 8)
            dst[(size_t)(n0 + j) * Md + k0 + tx] = __float2half_rn(tile[tx][j]);
    }
}

// ---------------- layer-1 GEMM: persistent, mma.sync fp16, 3-stage pipeline ----------------
// grid (GRIDX, 4): each CTA handles tiles blockIdx.x and blockIdx.x+GRIDX.
// y>>1 = branch (0:W1->g_h1h, 1:R1->g_r1h), y&1 = column half.
__global__ void __launch_bounds__(256, 2)
k_gemm1_mma(const float* __restrict__ b1, const float* __restrict__ rb1)
{
    extern __shared__ float sm[];
    __shared__ int soff[Ee+1];

    int tid = threadIdx.x;
    if (tid < Ee+1) soff[tid] = g_off[tid];
    __syncthreads();

    bool rotb = (blockIdx.y >= 2);
    int  half = blockIdx.y & 1;
    const __half* Wbase = (rotb ? g_r1w : g_w1h);
    const float*  bbase = (rotb ? rb1 : b1);
    __half*       dst   = rotb ? g_r1h : g_h1h;

    float* sbias = (float*)((char*)sm + NST*STAGE_B);
    uint32_t smU = s2u(sm);

    int wid = tid >> 5;
    int lane = tid & 31;
    int g = lane >> 2, tig = lane & 3;
    int warpM = wid & 3, warpN = wid >> 2;

    int row  = tid >> 1;
    int hsel = tid & 1;
    uint32_t wdst = smU + (uint32_t)row*(WPH*2) + hsel*32;
    uint32_t xdst = smU + (uint32_t)(128 + row)*(WPH*2) + hsel*32;

    uint32_t aoff[2];
    {
        int r16 = ((lane >> 3) & 1) * 8 + (lane & 7);
        int bhi = (lane >> 4) * 16;
        #pragma unroll
        for (int mt = 0; mt < 2; mt++) {
            int m = warpM*32 + mt*16 + r16;
            aoff[mt] = (uint32_t)m*(WPH*2) + bhi;
        }
    }
    uint32_t boff[4];
    {
        int tok = ((lane >> 4) * 8) + (lane & 7);
        int bhi = ((lane >> 3) & 1) * 16;
        #pragma unroll
        for (int p = 0; p < 4; p++) {
            int n = warpN*64 + p*16 + tok;
            boff[p] = (uint32_t)(128 + n)*(WPH*2) + bhi;
        }
    }

    for (int t0 = blockIdx.x; t0 < NTILES; t0 += GRIDX) {
        int p0 = t0 * TT;
        if (p0 >= soff[Ee]) break;
        int e = 0;
        while (e < Ee-1 && p0 >= soff[e+1]) e++;

        const __half* Wt   = Wbase + (size_t)(e*Md + half*128) * Fd;
        const float*  bias = bbase + e*Md + half*128;

        for (int i = tid; i < 128; i += 256) sbias[i] = bias[i];

        int t_x = g_sorted[p0 + row];
        uint32_t xsz = (t_x >= 0) ? 16u : 0u;
        const __half* xsrc = g_xh + (size_t)(t_x >= 0 ? t_x : 0) * Fd + hsel*16;
        const __half* wsrc = Wt + (size_t)row * Fd + hsel*16;

        auto load_stage = [&](int s, int b) {
            uint32_t bo = (uint32_t)b * STAGE_B;
            const __half* ws = wsrc + s*KC;
            cpa16(wdst + bo,      ws);
            cpa16(wdst + bo + 16, ws + 8);
            const __half* xs = xsrc + s*KC;
            cpa16z(xdst + bo,      xs,     xsz);
            cpa16z(xdst + bo + 16, xs + 8, xsz);
            asm volatile("cp.async.commit_group;" ::: "memory");
        };

        float c[2][8][4];
        #pragma unroll
        for (int mt = 0; mt < 2; mt++)
            #pragma unroll
            for (int nt = 0; nt < 8; nt++)
                #pragma unroll
                for (int r = 0; r < 4; r++) c[mt][nt][r] = 0.f;

        load_stage(0, 0);
        load_stage(1, 1);

        int b = 0, bn = 2;
        for (int s = 0; s < KSTEPS; s++) {
            if (s + 1 < KSTEPS) asm volatile("cp.async.wait_group 1;" ::: "memory");
            else                asm volatile("cp.async.wait_group 0;" ::: "memory");
            __syncthreads();
            if (s + 2 < KSTEPS) load_stage(s + 2, bn);

            uint32_t stU = smU + (uint32_t)b * STAGE_B;

            #pragma unroll
            for (int kk = 0; kk < 2; kk++) {
                uint32_t ko = kk*32;
                uint32_t a[2][4];
                ldsm4(a[0][0], a[0][1], a[0][2], a[0][3], stU + aoff[0] + ko);
                ldsm4(a[1][0], a[1][1], a[1][2], a[1][3], stU + aoff[1] + ko);

                uint32_t bb[8][2];
                #pragma unroll
                for (int p = 0; p < 4; p++) {
                    uint32_t r0, r1, r2, r3;
                    ldsm4(r0, r1, r2, r3, stU + boff[p] + ko);
                    bb[2*p+0][0] = r0; bb[2*p+0][1] = r1;
                    bb[2*p+1][0] = r2; bb[2*p+1][1] = r3;
                }
                #pragma unroll
                for (int mt = 0; mt < 2; mt++)
                    #pragma unroll
                    for (int nt = 0; nt < 8; nt++)
                        MMA16816(c[mt][nt], a[mt], bb[nt]);
            }
            b = (b + 1) % NST;
            bn = (bn + 1) % NST;
        }
        __syncthreads();

        // epilogue: bias + relu + fp16, stage through smem, coalesced store
        __half* ep = (__half*)sm;
        #pragma unroll
        for (int mt = 0; mt < 2; mt++) {
            int m = warpM*32 + mt*16 + g;
            float bz0 = sbias[m], bz1 = sbias[m + 8];
            #pragma unroll
            for (int nt = 0; nt < 8; nt++) {
                int n = warpN*64 + nt*8 + 2*tig;
                ep[(size_t)n*EPH + m]         = __float2half_rn(fmaxf(c[mt][nt][0] + bz0, 0.f));
                ep[(size_t)(n+1)*EPH + m]     = __float2half_rn(fmaxf(c[mt][nt][1] + bz0, 0.f));
                ep[(size_t)n*EPH + m + 8]     = __float2half_rn(fmaxf(c[mt][nt][2] + bz1, 0.f));
                ep[(size_t)(n+1)*EPH + m + 8] = __float2half_rn(fmaxf(c[mt][nt][3] + bz1, 0.f));
            }
        }
        __syncthreads();

        {
            int r2 = tid >> 1, h2 = tid & 1;
            const __half* srow = ep + (size_t)r2*EPH + h2*64;
            __half* drow = dst + (size_t)(p0 + r2)*Md + half*128 + h2*64;
            #pragma unroll
            for (int i = 0; i < 8; i++)
                *reinterpret_cast<uint4*>(drow + i*8) =
                    *reinterpret_cast<const uint4*>(srow + i*8);
        }
        __syncthreads();   // protect ep region before next tile's prologue
    }
}

// ---------------- tail2: mma layer2 + SIMT layers 3/4 + rot ----------------
__global__ void __launch_bounds__(256, 1)
k_tail2(const float* __restrict__ b2,
        const float* __restrict__ W3, const float* __restrict__ b3,
        const float* __restrict__ W4, const float* __restrict__ b4,
        const float* __restrict__ R2, const float* __restrict__ rb2,
        const int* __restrict__ lengths, float* __restrict__ out)
{
    extern __shared__ char smc[];
    __shared__ int soff[Ee+1];
    int tid = threadIdx.x;
    if (tid < Ee+1) soff[tid] = g_off[tid];
    __syncthreads();

    int p0 = blockIdx.x * TT;
    if (p0 >= soff[Ee]) return;
    int e = 0;
    while (e < Ee-1 && p0 >= soff[e+1]) e++;

    uint32_t smU = s2u(smc);
    float* sh2  = (float*)(smc + T2_SH2);
    float* sW3  = (float*)(smc + T2_SW3);
    float* sW4  = (float*)(smc + T2_SW4);
    float* sR2  = (float*)(smc + T2_SR2);
    float* sh3  = (float*)(smc + T2_SH3);
    float* sb2  = (float*)(smc + T2_SB2);
    float* sb3  = (float*)(smc + T2_SB3);
    float* sb4  = (float*)(smc + T2_SB4);
    float* srb2 = (float*)(smc + T2_SRB2);

    {
        int row = tid >> 1, hs = tid & 1;
        const __half* src = g_h1h + (size_t)(p0 + row)*Md + hs*128;
        uint32_t d = smU + T2_SH + (uint32_t)row*(T2_PH*2) + hs*256;
        #pragma unroll
        for (int i = 0; i < 16; i++) cpa16(d + i*16, src + i*8);
    }
    {
        int row = tid >> 2, hs = tid & 3;
        const __half* src = g_w2t + (size_t)e*64*Md + (size_t)row*Md + hs*64;
        uint32_t d = smU + T2_SW2 + (uint32_t)row*(T2_PH*2) + hs*128;
        #pragma unroll
        for (int i = 0; i < 8; i++) cpa16(d + i*16, src + i*8);
    }
    asm volatile("cp.async.commit_group;" ::: "memory");

    const float* gW3 = W3 + e*64*32;
    for (int i = tid; i < 64*32; i += 256) sW3[i] = gW3[i];
    const float* gW4 = W4 + e*32*14;
    for (int i = tid; i < 32*14; i += 256) sW4[i] = gW4[i];
    const float* gR2 = R2 + e*Md*3;
    for (int i = tid; i < Md*3; i += 256) sR2[i] = gR2[i];
    if (tid < 64) sb2[tid]  = b2[e*64 + tid];
    if (tid < 32) sb3[tid]  = b3[e*32 + tid];
    if (tid < 14) sb4[tid]  = b4[e*14 + tid];
    if (tid < 3)  srb2[tid] = rb2[e*3 + tid];

    asm volatile("cp.async.wait_group 0;" ::: "memory");
    __syncthreads();

    int wid = tid >> 5, lane = tid & 31;
    int g = lane >> 2, tig = lane & 3;
    int warpM = wid & 3, warpN = wid >> 2;

    uint32_t aoff[2];
    {
        int r16 = ((lane >> 3) & 1) * 8 + (lane & 7);
        int bhi = (lane >> 4) * 16;
        #pragma unroll
        for (int mt = 0; mt < 2; mt++) {
            int m = warpM*32 + mt*16 + r16;
            aoff[mt] = T2_SH + (uint32_t)m*(T2_PH*2) + bhi;
        }
    }
    uint32_t boff[2];
    {
        int nn = ((lane >> 4) * 8) + (lane & 7);
        int bhi = ((lane >> 3) & 1) * 16;
        #pragma unroll
        for (int p = 0; p < 2; p++) {
            int n = warpN*32 + p*16 + nn;
            boff[p] = T2_SW2 + (uint32_t)n*(T2_PH*2) + bhi;
        }
    }

    float c[2][4][4];
    #pragma unroll
    for (int mt = 0; mt < 2; mt++)
        #pragma unroll
        for (int nt = 0; nt < 4; nt++)
            #pragma unroll
            for (int r = 0; r < 4; r++) c[mt][nt][r] = 0.f;

    #pragma unroll
    for (int kk = 0; kk < 16; kk++) {
        uint32_t ko = kk*32;
        uint32_t a[2][4];
        ldsm4(a[0][0], a[0][1], a[0][2], a[0][3], smU + aoff[0] + ko);
        ldsm4(a[1][0], a[1][1], a[1][2], a[1][3], smU + aoff[1] + ko);
        uint32_t bb[4][2];
        #pragma unroll
        for (int p = 0; p < 2; p++) {
            uint32_t r0, r1, r2, r3;
            ldsm4(r0, r1, r2, r3, smU + boff[p] + ko);
            bb[2*p+0][0] = r0; bb[2*p+0][1] = r1;
            bb[2*p+1][0] = r2; bb[2*p+1][1] = r3;
        }
        #pragma unroll
        for (int mt = 0; mt < 2; mt++)
            #pragma unroll
            for (int nt = 0; nt < 4; nt++)
                MMA16816(c[mt][nt], a[mt], bb[nt]);
    }

    #pragma unroll
    for (int mt = 0; mt < 2; mt++) {
        int m0 = warpM*32 + mt*16 + g;
        #pragma unroll
        for (int nt = 0; nt < 4; nt++) {
            int n = warpN*32 + nt*8 + 2*tig;
            float bz0 = sb2[n], bz1 = sb2[n+1];
            sh2[(size_t)m0*68 + n]         = fmaxf(c[mt][nt][0] + bz0, 0.f);
            sh2[(size_t)m0*68 + n + 1]     = fmaxf(c[mt][nt][1] + bz1, 0.f);
            sh2[(size_t)(m0+8)*68 + n]     = fmaxf(c[mt][nt][2] + bz0, 0.f);
            sh2[(size_t)(m0+8)*68 + n + 1] = fmaxf(c[mt][nt][3] + bz1, 0.f);
        }
    }
    __syncthreads();

    float* h3w = sh3 + wid*36;
    for (int it = 0; it < 16; it++) {
        int p = p0 + wid*16 + it;
        int t = g_sorted[p];
        if (t < 0) continue;

        const float* h2row = sh2 + (size_t)(wid*16 + it)*68;

        float a = sb3[lane];
        #pragma unroll
        for (int h = 0; h < 64; h++) a += h2row[h] * sW3[h*32 + lane];
        h3w[lane] = fmaxf(a, 0.f);
        __syncwarp();

        float y = 0.f;
        if (lane < 14) {
            y = sb4[lane];
            #pragma unroll
            for (int gg = 0; gg < 32; gg++) y += h3w[gg] * sW4[gg*14 + lane];
        }

        float r0 = 0.f, r1v = 0.f, r2 = 0.f;
        {
            uint4 rv = *reinterpret_cast<const uint4*>(g_r1h + (size_t)p*Md + lane*8);
            const __half2* hp = reinterpret_cast<const __half2*>(&rv);
            #pragma unroll
            for (int u = 0; u < 4; u++) {
                float2 f = __half22float2(hp[u]);
                int m = lane*8 + 2*u;
                r0  += f.x * sR2[m*3 + 0] + f.y * sR2[(m+1)*3 + 0];
                r1v += f.x * sR2[m*3 + 1] + f.y * sR2[(m+1)*3 + 1];
                r2  += f.x * sR2[m*3 + 2] + f.y * sR2[(m+1)*3 + 2];
            }
        }
        #pragma unroll
        for (int s = 16; s > 0; s >>= 1) {
            r0  += __shfl_xor_sync(0xffffffff, r0, s);
            r1v += __shfl_xor_sync(0xffffffff, r1v, s);
            r2  += __shfl_xor_sync(0xffffffff, r2, s);
        }

        int b = t >> 9, n = t & (Nn - 1);
        bool masked = (n >= lengths[b]);
        float* op = out + (size_t)t*OUTD;
        if (masked) {
            if (lane < OUTD) op[lane] = EPSV;
        } else {
            if (lane < 14) op[lane] = y;
            if (lane == 0) {
                op[14] = r0  + srb2[0];
                op[15] = r1v + srb2[1];
                op[16] = r2  + srb2[2];
            }
        }
    }
}

extern "C" void kernel_launch(void* const* d_in, const int* in_sizes, int n_in,
                              void* d_out, int out_size) {
    const float* nodes   = (const float*)d_in[0];
    const int*   sem     = (const int*)  d_in[1];
    const int*   lengths = (const int*)  d_in[2];
    const float* W1 = (const float*)d_in[3];  const float* b1  = (const float*)d_in[4];
    const float* W2 = (const float*)d_in[5];  const float* b2  = (const float*)d_in[6];
    const float* W3 = (const float*)d_in[7];  const float* b3  = (const float*)d_in[8];
    const float* W4 = (const float*)d_in[9];  const float* b4  = (const float*)d_in[10];
    const float* R1 = (const float*)d_in[11]; const float* rb1 = (const float*)d_in[12];
    const float* R2 = (const float*)d_in[13]; const float* rb2 = (const float*)d_in[14];
    float* out = (float*)d_out;

    cudaFuncSetAttribute(k_gemm1_mma, cudaFuncAttributeMaxDynamicSharedMemorySize, GEMM_SMEM);
    cudaFuncSetAttribute(k_tail2, cudaFuncAttributeMaxDynamicSharedMemorySize, TAIL2_SMEM);

    k_count  <<<Tt/256, 256>>>(sem);
    k_offsets<<<1, 256>>>();
    k_scatter<<<Tt/256, 256>>>(sem);
    k_prep   <<<PREP_BLKS, 256>>>(nodes, W1, R1, W2);
    {
        dim3 g1(GRIDX, 4);
        k_gemm1_mma<<<g1, 256, GEMM_SMEM>>>(b1, rb1);
    }
    k_tail2<<<NTILES, 256, TAIL2_SMEM>>>(b2, W3, b3, W4, b4, R2, rb2, lengths, out);
}

// round 17
// speedup vs baseline: 1.4992x; 1.1152x over previous
#include <cuda_runtime.h>
#include <cuda_fp16.h>
#include <cstdint>

#define Bq   32
#define Nn   512
#define Tt   (Bq*Nn)          // 16384 tokens
#define Fd   1024
#define Md   256
#define Ee   8
#define TT   128              // token tile
#define NTILES (Tt/TT + Ee)   // 136 max padded tiles
#define SORT_SZ (Tt + Ee*TT)  // 17408
#define OUTD 17
#define EPSV 1e-8f

// layer-1 GEMM tiling (fp16 operands, fp32 accum)
#define KC 32                 // K halves per stage
#define KSTEPS (Fd/KC)        // 32
#define WPH 40                // stage row pitch in halves (32 + 8 pad)
#define STAGE_B (256*WPH*2)   // 20480 B
#define NST 3
#define EPH 136               // epilogue pitch (halves)
#define GEMM_SMEM (NST*STAGE_B + 512)   // 61952

// tail2 smem layout (bytes)
#define T2_PH 264                       // h1 / w2t row pitch in halves
#define T2_SH    0                      // 128 x 264 half
#define T2_SW2   (T2_SH + 128*T2_PH*2)  // 64 x 264 half
#define T2_SH2   (T2_SW2 + 64*T2_PH*2)  // 128 x 68 float
#define T2_SW3   (T2_SH2 + 128*68*4)
#define T2_SW4   (T2_SW3 + 64*32*4)
#define T2_SR2   (T2_SW4 + 32*14*4)
#define T2_SH3   (T2_SR2 + 256*3*4)
#define T2_SB2   (T2_SH3 + 8*36*4)
#define T2_SB3   (T2_SB2 + 64*4)
#define T2_SB4   (T2_SB3 + 32*4)
#define T2_SRB2  (T2_SB4 + 14*4)
#define TAIL2_SMEM (T2_SRB2 + 16*4)

// merged prep grid split: first 64 blocks = sort, then xh / wt / w2t
#define SORT_BLKS     64
#define PREP_XH_BLKS  (Tt*Fd/8/256)     // 8192
#define PREP_WT_BLKS  4096
#define PREP_W2T_BLKS 128
#define PREP_BLKS (SORT_BLKS + PREP_XH_BLKS + PREP_WT_BLKS + PREP_W2T_BLKS)

// ---------------- device scratch ----------------
__device__ int    g_partial[SORT_BLKS][Ee];
__device__ int    g_fill[Ee];
__device__ int    g_off[Ee+1];
__device__ int    g_sorted[SORT_SZ];
__device__ int    g_tick, g_flag, g_fin;   // zero-initialized; reset each launch
__device__ __half g_h1h[(size_t)SORT_SZ*Md];
__device__ __half g_r1h[(size_t)SORT_SZ*Md];
__device__ __half g_w1h[(size_t)Ee*Md*Fd];   // W1^T [e][n][k] fp16
__device__ __half g_r1w[(size_t)Ee*Md*Fd];   // R1^T
__device__ __half g_w2t[(size_t)Ee*64*Md];   // W2^T [e][n][k] fp16
__device__ __half g_xh [(size_t)Tt*Fd];      // nodes in fp16

// ---------------- helpers ----------------
__device__ __forceinline__ uint32_t s2u(const void* p) {
    return (uint32_t)__cvta_generic_to_shared((void*)p);
}
__device__ __forceinline__ void cpa16(uint32_t d, const void* s) {
    asm volatile("cp.async.cg.shared.global [%0], [%1], 16;" :: "r"(d), "l"(s));
}
__device__ __forceinline__ void cpa16z(uint32_t d, const void* s, uint32_t sz) {
    asm volatile("cp.async.cg.shared.global [%0], [%1], 16, %2;" :: "r"(d), "l"(s), "r"(sz));
}
__device__ __forceinline__ void ldsm4(uint32_t &r0, uint32_t &r1, uint32_t &r2, uint32_t &r3,
                                      uint32_t addr) {
    asm volatile("ldmatrix.sync.aligned.m8n8.x4.shared.b16 {%0,%1,%2,%3}, [%4];"
                 : "=r"(r0), "=r"(r1), "=r"(r2), "=r"(r3) : "r"(addr));
}
#define MMA16816(C, A, B)                                                        \
    asm volatile(                                                                \
        "mma.sync.aligned.m16n8k16.row.col.f32.f16.f16.f32 "                     \
        "{%0,%1,%2,%3}, {%4,%5,%6,%7}, {%8,%9}, {%0,%1,%2,%3};"                  \
        : "+f"((C)[0]), "+f"((C)[1]), "+f"((C)[2]), "+f"((C)[3])                 \
        : "r"((A)[0]), "r"((A)[1]), "r"((A)[2]), "r"((A)[3]),                    \
          "r"((B)[0]), "r"((B)[1]))

// ---------------- merged prep + sort ----------------
__global__ void k_prep(const int* __restrict__ sem,
                       const float* __restrict__ nodes,
                       const float* __restrict__ W1, const float* __restrict__ R1,
                       const float* __restrict__ W2) {
    int bid = blockIdx.x;
    int tid = threadIdx.x;

    if (bid < SORT_BLKS) {
        // ---- phase 1: per-block histogram ----
        __shared__ int h[Ee];
        __shared__ int s_last;
        if (tid < Ee) h[tid] = 0;
        __syncthreads();
        int myTok = bid*256 + tid;
        int myE = sem[myTok];
        atomicAdd(&h[myE], 1);
        __syncthreads();
        if (tid < Ee) g_partial[bid][tid] = h[tid];
        __threadfence();
        if (tid == 0) {
            int t = atomicAdd(&g_tick, 1);
            s_last = (t == SORT_BLKS-1);
        }
        __syncthreads();

        if (s_last) {
            // ---- phase 2 (last block): offsets, sentinels, fills ----
            __threadfence();
            __shared__ int scnt[Ee];
            __shared__ int so[Ee+1];
            if (tid < Ee) {
                int s = 0;
                for (int b = 0; b < SORT_BLKS; b++) s += g_partial[b][tid];
                scnt[tid] = s;
                g_fill[tid] = 0;
            }
            __syncthreads();
            if (tid == 0) {
                int acc = 0;
                for (int e = 0; e < Ee; e++) {
                    so[e] = acc; g_off[e] = acc;
                    acc += ((scnt[e] + TT - 1) / TT) * TT;
                }
                so[Ee] = acc; g_off[Ee] = acc;
            }
            __syncthreads();
            for (int e = 0; e < Ee; e++) {
                int cnt = scnt[e], base = so[e], padded = so[e+1] - base;
                for (int i = cnt + tid; i < padded; i += 256)
                    g_sorted[base + i] = -1;
            }
            __threadfence();
            if (tid == 0) atomicExch(&g_flag, 1);
        } else {
            if (tid == 0) {
                while (atomicAdd(&g_flag, 0) == 0) { }
            }
            __syncthreads();
            __threadfence();
        }

        // ---- phase 3: scatter own tokens ----
        {
            int pos = g_off[myE] + atomicAdd(&g_fill[myE], 1);
            g_sorted[pos] = myTok;
        }
        __threadfence();
        __syncthreads();
        if (tid == 0) {
            int f = atomicAdd(&g_fin, 1);
            if (f == SORT_BLKS-1) {        // all blocks done: reset for next replay
                g_tick = 0; g_flag = 0; g_fin = 0;
                __threadfence();
            }
        }
        return;
    }

    int pbid = bid - SORT_BLKS;
    if (pbid < PREP_XH_BLKS) {
        size_t i = ((size_t)pbid*256 + tid) * 8;
        float4 v0 = *reinterpret_cast<const float4*>(nodes + i);
        float4 v1 = *reinterpret_cast<const float4*>(nodes + i + 4);
        __half2 h[4];
        h[0] = __floats2half2_rn(v0.x, v0.y);
        h[1] = __floats2half2_rn(v0.z, v0.w);
        h[2] = __floats2half2_rn(v1.x, v1.y);
        h[3] = __floats2half2_rn(v1.z, v1.w);
        *reinterpret_cast<uint4*>(g_xh + i) = *reinterpret_cast<uint4*>(h);
        return;
    }

    __shared__ float tile[32][33];
    int tx = tid & 31, ty = tid >> 5;

    if (pbid < PREP_XH_BLKS + PREP_WT_BLKS) {
        int bz = pbid - PREP_XH_BLKS;         // [0, 4096)
        int z   = bz >> 8;                    // mat*8 + e
        int rem = bz & 255;
        int k0 = (rem & 31) * 32;
        int n0 = (rem >> 5) * 32;
        int mat = z >> 3, e = z & 7;
        const float* src = (mat ? R1 : W1) + (size_t)e * Fd * Md;
        __half*      dst = (mat ? g_r1w : g_w1h) + (size_t)e * Md * Fd;
        for (int j = ty; j < 32; j += 8)
            tile[j][tx] = src[(size_t)(k0 + j) * Md + n0 + tx];
        __syncthreads();
        for (int j = ty; j < 32; j += 8)
            dst[(size_t)(n0 + j) * Fd + k0 + tx] = __float2half_rn(tile[tx][j]);
        return;
    }

    {
        int bz = pbid - PREP_XH_BLKS - PREP_WT_BLKS;   // [0, 128)
        int k0 = (bz & 7) * 32;
        int n0 = ((bz >> 3) & 1) * 32;
        int e  = bz >> 4;
        const float* src = W2 + (size_t)e * Md * 64;
        __half*      dst = g_w2t + (size_t)e * 64 * Md;
        for (int j = ty; j < 32; j += 8)
            tile[j][tx] = src[(size_t)(k0 + j) * 64 + n0 + tx];
        __syncthreads();
        for (int j = ty; j < 32; j += 8)
            dst[(size_t)(n0 + j) * Md + k0 + tx] = __float2half_rn(tile[tx][j]);
    }
}

// ---------------- layer-1 GEMM: mma.sync fp16 + ldmatrix, 3-stage pipeline ----------------
// grid (NTILES, 4): y>>1 = branch (0:W1->g_h1h, 1:R1->g_r1h), y&1 = column half.
__global__ void __launch_bounds__(256, 2)
k_gemm1_mma(const float* __restrict__ b1, const float* __restrict__ rb1)
{
    extern __shared__ float sm[];
    __shared__ int soff[Ee+1];

    int tid = threadIdx.x;
    if (tid < Ee+1) soff[tid] = g_off[tid];
    __syncthreads();

    int p0 = blockIdx.x * TT;
    if (p0 >= soff[Ee]) return;
    int e = 0;
    while (e < Ee-1 && p0 >= soff[e+1]) e++;

    bool rotb = (blockIdx.y >= 2);
    int  half = blockIdx.y & 1;
    const __half* Wt   = (rotb ? g_r1w : g_w1h) + (size_t)(e*Md + half*128) * Fd;
    const float*  bias = (rotb ? rb1 : b1) + e*Md + half*128;
    __half*       dst  = rotb ? g_r1h : g_h1h;

    float* sbias = (float*)((char*)sm + NST*STAGE_B);
    for (int i = tid; i < 128; i += 256) sbias[i] = bias[i];

    int row  = tid >> 1;
    int hsel = tid & 1;
    int t_x = g_sorted[p0 + row];
    uint32_t xsz = (t_x >= 0) ? 16u : 0u;
    const __half* xsrc = g_xh + (size_t)(t_x >= 0 ? t_x : 0) * Fd + hsel*16;
    const __half* wsrc = Wt + (size_t)row * Fd + hsel*16;

    uint32_t smU  = s2u(sm);
    uint32_t wdst = smU + (uint32_t)row*(WPH*2) + hsel*32;
    uint32_t xdst = smU + (uint32_t)(128 + row)*(WPH*2) + hsel*32;

    auto load_stage = [&](int s, int b) {
        uint32_t bo = (uint32_t)b * STAGE_B;
        const __half* ws = wsrc + s*KC;
        cpa16(wdst + bo,      ws);
        cpa16(wdst + bo + 16, ws + 8);
        const __half* xs = xsrc + s*KC;
        cpa16z(xdst + bo,      xs,     xsz);
        cpa16z(xdst + bo + 16, xs + 8, xsz);
        asm volatile("cp.async.commit_group;" ::: "memory");
    };

    int wid = tid >> 5;
    int lane = tid & 31;
    int g = lane >> 2, tig = lane & 3;
    int warpM = wid & 3, warpN = wid >> 2;

    uint32_t aoff[2];
    {
        int r16 = ((lane >> 3) & 1) * 8 + (lane & 7);
        int bhi = (lane >> 4) * 16;
        #pragma unroll
        for (int mt = 0; mt < 2; mt++) {
            int m = warpM*32 + mt*16 + r16;
            aoff[mt] = (uint32_t)m*(WPH*2) + bhi;
        }
    }
    uint32_t boff[4];
    {
        int tok = ((lane >> 4) * 8) + (lane & 7);
        int bhi = ((lane >> 3) & 1) * 16;
        #pragma unroll
        for (int p = 0; p < 4; p++) {
            int n = warpN*64 + p*16 + tok;
            boff[p] = (uint32_t)(128 + n)*(WPH*2) + bhi;
        }
    }

    float c[2][8][4];
    #pragma unroll
    for (int mt = 0; mt < 2; mt++)
        #pragma unroll
        for (int nt = 0; nt < 8; nt++)
            #pragma unroll
            for (int r = 0; r < 4; r++) c[mt][nt][r] = 0.f;

    load_stage(0, 0);
    load_stage(1, 1);

    int b = 0, bn = 2;   // compute buffer, next-load buffer
    for (int s = 0; s < KSTEPS; s++) {
        if (s + 1 < KSTEPS) asm volatile("cp.async.wait_group 1;" ::: "memory");
        else                asm volatile("cp.async.wait_group 0;" ::: "memory");
        __syncthreads();
        if (s + 2 < KSTEPS) load_stage(s + 2, bn);

        uint32_t stU = smU + (uint32_t)b * STAGE_B;

        #pragma unroll
        for (int kk = 0; kk < 2; kk++) {
            uint32_t ko = kk*32;
            uint32_t a[2][4];
            ldsm4(a[0][0], a[0][1], a[0][2], a[0][3], stU + aoff[0] + ko);
            ldsm4(a[1][0], a[1][1], a[1][2], a[1][3], stU + aoff[1] + ko);

            uint32_t bb[8][2];
            #pragma unroll
            for (int p = 0; p < 4; p++) {
                uint32_t r0, r1, r2, r3;
                ldsm4(r0, r1, r2, r3, stU + boff[p] + ko);
                bb[2*p+0][0] = r0; bb[2*p+0][1] = r1;
                bb[2*p+1][0] = r2; bb[2*p+1][1] = r3;
            }
            #pragma unroll
            for (int mt = 0; mt < 2; mt++)
                #pragma unroll
                for (int nt = 0; nt < 8; nt++)
                    MMA16816(c[mt][nt], a[mt], bb[nt]);
        }
        b = (b + 1) % NST;
        bn = (bn + 1) % NST;
    }
    __syncthreads();

    // epilogue: bias + relu + fp16, stage through smem, coalesced store
    __half* ep = (__half*)sm;
    #pragma unroll
    for (int mt = 0; mt < 2; mt++) {
        int m = warpM*32 + mt*16 + g;
        float bz0 = sbias[m], bz1 = sbias[m + 8];
        #pragma unroll
        for (int nt = 0; nt < 8; nt++) {
            int n = warpN*64 + nt*8 + 2*tig;
            ep[(size_t)n*EPH + m]         = __float2half_rn(fmaxf(c[mt][nt][0] + bz0, 0.f));
            ep[(size_t)(n+1)*EPH + m]     = __float2half_rn(fmaxf(c[mt][nt][1] + bz0, 0.f));
            ep[(size_t)n*EPH + m + 8]     = __float2half_rn(fmaxf(c[mt][nt][2] + bz1, 0.f));
            ep[(size_t)(n+1)*EPH + m + 8] = __float2half_rn(fmaxf(c[mt][nt][3] + bz1, 0.f));
        }
    }
    __syncthreads();

    {
        int r2 = tid >> 1, h2 = tid & 1;
        const __half* srow = ep + (size_t)r2*EPH + h2*64;
        __half* drow = dst + (size_t)(p0 + r2)*Md + half*128 + h2*64;
        #pragma unroll
        for (int i = 0; i < 8; i++)
            *reinterpret_cast<uint4*>(drow + i*8) =
                *reinterpret_cast<const uint4*>(srow + i*8);
    }
}

// ---------------- tail2: mma layer2 + SIMT layers 3/4 + rot ----------------
__global__ void __launch_bounds__(256, 1)
k_tail2(const float* __restrict__ b2,
        const float* __restrict__ W3, const float* __restrict__ b3,
        const float* __restrict__ W4, const float* __restrict__ b4,
        const float* __restrict__ R2, const float* __restrict__ rb2,
        const int* __restrict__ lengths, float* __restrict__ out)
{
    extern __shared__ char smc[];
    __shared__ int soff[Ee+1];
    int tid = threadIdx.x;
    if (tid < Ee+1) soff[tid] = g_off[tid];
    __syncthreads();

    int p0 = blockIdx.x * TT;
    if (p0 >= soff[Ee]) return;
    int e = 0;
    while (e < Ee-1 && p0 >= soff[e+1]) e++;

    uint32_t smU = s2u(smc);
    float* sh2  = (float*)(smc + T2_SH2);
    float* sW3  = (float*)(smc + T2_SW3);
    float* sW4  = (float*)(smc + T2_SW4);
    float* sR2  = (float*)(smc + T2_SR2);
    float* sh3  = (float*)(smc + T2_SH3);
    float* sb2  = (float*)(smc + T2_SB2);
    float* sb3  = (float*)(smc + T2_SB3);
    float* sb4  = (float*)(smc + T2_SB4);
    float* srb2 = (float*)(smc + T2_SRB2);

    {
        int row = tid >> 1, hs = tid & 1;
        const __half* src = g_h1h + (size_t)(p0 + row)*Md + hs*128;
        uint32_t d = smU + T2_SH + (uint32_t)row*(T2_PH*2) + hs*256;
        #pragma unroll
        for (int i = 0; i < 16; i++) cpa16(d + i*16, src + i*8);
    }
    {
        int row = tid >> 2, hs = tid & 3;
        const __half* src = g_w2t + (size_t)e*64*Md + (size_t)row*Md + hs*64;
        uint32_t d = smU + T2_SW2 + (uint32_t)row*(T2_PH*2) + hs*128;
        #pragma unroll
        for (int i = 0; i < 8; i++) cpa16(d + i*16, src + i*8);
    }
    asm volatile("cp.async.commit_group;" ::: "memory");

    const float* gW3 = W3 + e*64*32;
    for (int i = tid; i < 64*32; i += 256) sW3[i] = gW3[i];
    const float* gW4 = W4 + e*32*14;
    for (int i = tid; i < 32*14; i += 256) sW4[i] = gW4[i];
    const float* gR2 = R2 + e*Md*3;
    for (int i = tid; i < Md*3; i += 256) sR2[i] = gR2[i];
    if (tid < 64) sb2[tid]  = b2[e*64 + tid];
    if (tid < 32) sb3[tid]  = b3[e*32 + tid];
    if (tid < 14) sb4[tid]  = b4[e*14 + tid];
    if (tid < 3)  srb2[tid] = rb2[e*3 + tid];

    asm volatile("cp.async.wait_group 0;" ::: "memory");
    __syncthreads();

    int wid = tid >> 5, lane = tid & 31;
    int g = lane >> 2, tig = lane & 3;
    int warpM = wid & 3, warpN = wid >> 2;

    uint32_t aoff[2];
    {
        int r16 = ((lane >> 3) & 1) * 8 + (lane & 7);
        int bhi = (lane >> 4) * 16;
        #pragma unroll
        for (int mt = 0; mt < 2; mt++) {
            int m = warpM*32 + mt*16 + r16;
            aoff[mt] = T2_SH + (uint32_t)m*(T2_PH*2) + bhi;
        }
    }
    uint32_t boff[2];
    {
        int nn = ((lane >> 4) * 8) + (lane & 7);
        int bhi = ((lane >> 3) & 1) * 16;
        #pragma unroll
        for (int p = 0; p < 2; p++) {
            int n = warpN*32 + p*16 + nn;
            boff[p] = T2_SW2 + (uint32_t)n*(T2_PH*2) + bhi;
        }
    }

    float c[2][4][4];
    #pragma unroll
    for (int mt = 0; mt < 2; mt++)
        #pragma unroll
        for (int nt = 0; nt < 4; nt++)
            #pragma unroll
            for (int r = 0; r < 4; r++) c[mt][nt][r] = 0.f;

    #pragma unroll
    for (int kk = 0; kk < 16; kk++) {
        uint32_t ko = kk*32;
        uint32_t a[2][4];
        ldsm4(a[0][0], a[0][1], a[0][2], a[0][3], smU + aoff[0] + ko);
        ldsm4(a[1][0], a[1][1], a[1][2], a[1][3], smU + aoff[1] + ko);
        uint32_t bb[4][2];
        #pragma unroll
        for (int p = 0; p < 2; p++) {
            uint32_t r0, r1, r2, r3;
            ldsm4(r0, r1, r2, r3, smU + boff[p] + ko);
            bb[2*p+0][0] = r0; bb[2*p+0][1] = r1;
            bb[2*p+1][0] = r2; bb[2*p+1][1] = r3;
        }
        #pragma unroll
        for (int mt = 0; mt < 2; mt++)
            #pragma unroll
            for (int nt = 0; nt < 4; nt++)
                MMA16816(c[mt][nt], a[mt], bb[nt]);
    }

    #pragma unroll
    for (int mt = 0; mt < 2; mt++) {
        int m0 = warpM*32 + mt*16 + g;
        #pragma unroll
        for (int nt = 0; nt < 4; nt++) {
            int n = warpN*32 + nt*8 + 2*tig;
            float bz0 = sb2[n], bz1 = sb2[n+1];
            sh2[(size_t)m0*68 + n]         = fmaxf(c[mt][nt][0] + bz0, 0.f);
            sh2[(size_t)m0*68 + n + 1]     = fmaxf(c[mt][nt][1] + bz1, 0.f);
            sh2[(size_t)(m0+8)*68 + n]     = fmaxf(c[mt][nt][2] + bz0, 0.f);
            sh2[(size_t)(m0+8)*68 + n + 1] = fmaxf(c[mt][nt][3] + bz1, 0.f);
        }
    }
    __syncthreads();

    float* h3w = sh3 + wid*36;
    for (int it = 0; it < 16; it++) {
        int p = p0 + wid*16 + it;
        int t = g_sorted[p];
        if (t < 0) continue;

        const float* h2row = sh2 + (size_t)(wid*16 + it)*68;

        float a = sb3[lane];
        #pragma unroll
        for (int h = 0; h < 64; h++) a += h2row[h] * sW3[h*32 + lane];
        h3w[lane] = fmaxf(a, 0.f);
        __syncwarp();

        float y = 0.f;
        if (lane < 14) {
            y = sb4[lane];
            #pragma unroll
            for (int gg = 0; gg < 32; gg++) y += h3w[gg] * sW4[gg*14 + lane];
        }

        float r0 = 0.f, r1v = 0.f, r2 = 0.f;
        {
            uint4 rv = *reinterpret_cast<const uint4*>(g_r1h + (size_t)p*Md + lane*8);
            const __half2* hp = reinterpret_cast<const __half2*>(&rv);
            #pragma unroll
            for (int u = 0; u < 4; u++) {
                float2 f = __half22float2(hp[u]);
                int m = lane*8 + 2*u;
                r0  += f.x * sR2[m*3 + 0] + f.y * sR2[(m+1)*3 + 0];
                r1v += f.x * sR2[m*3 + 1] + f.y * sR2[(m+1)*3 + 1];
                r2  += f.x * sR2[m*3 + 2] + f.y * sR2[(m+1)*3 + 2];
            }
        }
        #pragma unroll
        for (int s = 16; s > 0; s >>= 1) {
            r0  += __shfl_xor_sync(0xffffffff, r0, s);
            r1v += __shfl_xor_sync(0xffffffff, r1v, s);
            r2  += __shfl_xor_sync(0xffffffff, r2, s);
        }

        int b = t >> 9, n = t & (Nn - 1);
        bool masked = (n >= lengths[b]);
        float* op = out + (size_t)t*OUTD;
        if (masked) {
            if (lane < OUTD) op[lane] = EPSV;
        } else {
            if (lane < 14) op[lane] = y;
            if (lane == 0) {
                op[14] = r0  + srb2[0];
                op[15] = r1v + srb2[1];
                op[16] = r2  + srb2[2];
            }
        }
    }
}

extern "C" void kernel_launch(void* const* d_in, const int* in_sizes, int n_in,
                              void* d_out, int out_size) {
    const float* nodes   = (const float*)d_in[0];
    const int*   sem     = (const int*)  d_in[1];
    const int*   lengths = (const int*)  d_in[2];
    const float* W1 = (const float*)d_in[3];  const float* b1  = (const float*)d_in[4];
    const float* W2 = (const float*)d_in[5];  const float* b2  = (const float*)d_in[6];
    const float* W3 = (const float*)d_in[7];  const float* b3  = (const float*)d_in[8];
    const float* W4 = (const float*)d_in[9];  const float* b4  = (const float*)d_in[10];
    const float* R1 = (const float*)d_in[11]; const float* rb1 = (const float*)d_in[12];
    const float* R2 = (const float*)d_in[13]; const float* rb2 = (const float*)d_in[14];
    float* out = (float*)d_out;

    cudaFuncSetAttribute(k_gemm1_mma, cudaFuncAttributeMaxDynamicSharedMemorySize, GEMM_SMEM);
    cudaFuncSetAttribute(k_tail2, cudaFuncAttributeMaxDynamicSharedMemorySize, TAIL2_SMEM);

    k_prep<<<PREP_BLKS, 256>>>(sem, nodes, W1, R1, W2);
    {
        dim3 g1(NTILES, 4);
        k_gemm1_mma<<<g1, 256, GEMM_SMEM>>>(b1, rb1);
    }
    k_tail2<<<NTILES, 256, TAIL2_SMEM>>>(b2, W3, b3, W4, b4, R2, rb2, lengths, out);
}